// round 13
// baseline (speedup 1.0000x reference)
#include <cuda_runtime.h>
#include <math.h>

// B,H,L,D = 4,8,2048,64 ; FACTOR=5 -> sample_k = n_top = 40
#define Bq    4
#define Hq    8
#define Lq    2048
#define Dq    64
#define BH    (Bq*Hq)
#define SK    40
#define NT    40
#define NP    4            // K slices for k_M2
#define SL    (Lq/NP)      // 512 rows per slice
#define ZSP   4            // l-splits per (p,bh) in k_M2
#define ZL    (Lq/ZSP)     // 512 queries per z
#define LMAX  (ZL*SK)      // staged list worst case
#define NCH   64           // cumsum chunks
#define CHLEN (Lq/NCH)     // 32
#define NJT   16           // j-tiles (of 128) for fused score+AV
#define JT    (Lq/NJT)     // 128
#define SMEM_M2  (SL*Dq*4 + (ZL+1+3)*4 + LMAX*4)
// sav smem offsets (bytes): qs4 | kt | P | Vs | mtop | dsum | ucnt
#define SAV_QS   0
#define SAV_KT   (SAV_QS + NT*16*16)
#define SAV_P    (SAV_KT + JT*65*4)
#define SAV_VS   (SAV_P  + NT*JT*4)
#define SAV_MT   (SAV_VS + JT*Dq*4)
#define SAV_DS   (SAV_MT + NT*4)
#define SAV_UC   (SAV_DS + NT*4)
#define SMEM_SAV (SAV_UC + 64)

// ---- device scratch (no allocations allowed) ----
__device__ int    g_off[NP][Lq+1];     // per-slice offsets (zero-based)
__device__ int    g_list[NP][Lq*SK];   // per-slice sample lists
__device__ float2 g_part2[NP*BH*Lq];
__device__ int    g_top[BH*NT];        // sorted desc by row index
__device__ float  g_den[BH*NT];
__device__ float  g_part[BH*NJT*NT*Dq];
__device__ float  g_csum[BH*NCH*Dq];

// ---------------------------------------------------------------------------
// k_prep: per-slice count + block scan + fill, all in one kernel (grid NP).
// Each thread owns 2 queries.
// ---------------------------------------------------------------------------
__global__ void __launch_bounds__(1024) k_prep(const int* __restrict__ I) {
    __shared__ int wsum[32];
    int p = blockIdx.x, tid = threadIdx.x, lane = tid & 31, wid = tid >> 5;
    int l0 = tid * 2;

    const int* r0 = I + (size_t)l0*SK;
    const int* r1 = r0 + SK;
    int c0 = 0, c1 = 0;
    #pragma unroll
    for (int s = 0; s < SK; ++s) c0 += ((r0[s] >> 9) == p);
    #pragma unroll
    for (int s = 0; s < SK; ++s) c1 += ((r1[s] >> 9) == p);
    int s2 = c0 + c1;

    // block-wide exclusive scan of s2
    int v = s2;
    #pragma unroll
    for (int o = 1; o < 32; o <<= 1) {
        int t = __shfl_up_sync(0xffffffffu, v, o);
        if (lane >= o) v += t;
    }
    if (lane == 31) wsum[wid] = v;
    __syncthreads();
    if (wid == 0) {
        int x = wsum[lane];
        int inc = x;
        #pragma unroll
        for (int o = 1; o < 32; o <<= 1) {
            int t = __shfl_up_sync(0xffffffffu, inc, o);
            if (lane >= o) inc += t;
        }
        wsum[lane] = inc - x;          // exclusive
    }
    __syncthreads();
    int excl = v - s2 + wsum[wid];

    g_off[p][l0]   = excl;
    g_off[p][l0+1] = excl + c0;
    if (tid == 1023) g_off[p][Lq] = excl + s2;

    // fill
    int o0 = excl, o1 = excl + c0;
    #pragma unroll
    for (int s = 0; s < SK; ++s) {
        int j = r0[s];
        if ((j >> 9) == p) g_list[p][o0++] = j & (SL-1);
    }
    #pragma unroll
    for (int s = 0; s < SK; ++s) {
        int j = r1[s];
        if ((j >> 9) == p) g_list[p][o1++] = j & (SL-1);
    }
}

// ---------------------------------------------------------------------------
// k_M2: proven config + csum1 epilogue on the first 128 blocks.
// ---------------------------------------------------------------------------
__global__ void __launch_bounds__(1024) k_M2(const float* __restrict__ Q,
                                             const float* __restrict__ K,
                                             const float* __restrict__ V) {
    extern __shared__ float ks[];
    float4* ks4 = (float4*)ks;
    int* so = (int*)(ks + SL*Dq);
    int* sl = so + (ZL+1+3);
    int p = blockIdx.x, bh = blockIdx.y, z = blockIdx.z;
    int tid = threadIdx.x, warp = tid >> 5, lane = tid & 31;
    int g = lane >> 3, e = lane & 7;
    int zl0 = z*ZL;

    const float4* Ks = (const float4*)(K + ((size_t)bh*Lq + (size_t)p*SL)*Dq);
    for (int i = tid; i < SL*(Dq/4); i += 1024) ks4[i] = Ks[i];

    int sbeg = g_off[p][zl0];
    int send = g_off[p][zl0 + ZL];
    for (int i = tid; i <= ZL; i += 1024) so[i] = g_off[p][zl0 + i] - sbeg;
    for (int i = tid; i < send - sbeg; i += 1024) sl[i] = g_list[p][sbeg + i];
    __syncthreads();

    const float4* Q4 = (const float4*)Q;
    int l0 = zl0 + warp;
    #pragma unroll 1
    for (int i = 0; i < 16; i += 2) {
        int la = l0 + 32*i, lb = la + 32;
        int lla = warp + 32*i, llb = lla + 32;
        int a0 = so[lla], a1 = so[lla+1];
        int b0 = so[llb], b1 = so[llb+1];
        size_t qra = ((size_t)bh*Lq + la)*16;
        size_t qrb = ((size_t)bh*Lq + lb)*16;
        float4 qa0 = Q4[qra + e], qa1 = Q4[qra + e + 8];
        float4 qb0 = Q4[qrb + e], qb1 = Q4[qrb + e + 8];
        float mx0 = -INFINITY, sm0 = 0.f, mx1 = -INFINITY, sm1 = 0.f;
        int c0 = a0, c1 = b0;
        while (c0 < a1 || c1 < b1) {
            float pr0 = 0.f, pr1 = 0.f;
            bool v0 = false, v1 = false;
            if (c0 < a1) {
                int idx = c0 + g; v0 = idx < a1;
                int j = sl[v0 ? idx : a0];
                const float4* kb = ks4 + (j << 4);
                float4 x = kb[e], y = kb[e + 8];
                pr0 = qa0.x*x.x + qa0.y*x.y + qa0.z*x.z + qa0.w*x.w
                    + qa1.x*y.x + qa1.y*y.y + qa1.z*y.z + qa1.w*y.w;
            }
            if (c1 < b1) {
                int idx = c1 + g; v1 = idx < b1;
                int j = sl[v1 ? idx : b0];
                const float4* kb = ks4 + (j << 4);
                float4 x = kb[e], y = kb[e + 8];
                pr1 = qb0.x*x.x + qb0.y*x.y + qb0.z*x.z + qb0.w*x.w
                    + qb1.x*y.x + qb1.y*y.y + qb1.z*y.z + qb1.w*y.w;
            }
            pr0 += __shfl_xor_sync(0xffffffffu, pr0, 1);
            pr1 += __shfl_xor_sync(0xffffffffu, pr1, 1);
            pr0 += __shfl_xor_sync(0xffffffffu, pr0, 2);
            pr1 += __shfl_xor_sync(0xffffffffu, pr1, 2);
            pr0 += __shfl_xor_sync(0xffffffffu, pr0, 4);
            pr1 += __shfl_xor_sync(0xffffffffu, pr1, 4);
            if (v0) { mx0 = fmaxf(mx0, pr0); sm0 += pr0; }
            if (v1) { mx1 = fmaxf(mx1, pr1); sm1 += pr1; }
            c0 += 4; c1 += 4;
        }
        mx0 = fmaxf(mx0, __shfl_xor_sync(0xffffffffu, mx0, 8));
        mx0 = fmaxf(mx0, __shfl_xor_sync(0xffffffffu, mx0, 16));
        sm0 += __shfl_xor_sync(0xffffffffu, sm0, 8);
        sm0 += __shfl_xor_sync(0xffffffffu, sm0, 16);
        mx1 = fmaxf(mx1, __shfl_xor_sync(0xffffffffu, mx1, 8));
        mx1 = fmaxf(mx1, __shfl_xor_sync(0xffffffffu, mx1, 16));
        sm1 += __shfl_xor_sync(0xffffffffu, sm1, 8);
        sm1 += __shfl_xor_sync(0xffffffffu, sm1, 16);
        if (lane == 0) {
            g_part2[((size_t)p*BH + bh)*Lq + la] = make_float2(mx0, sm0);
            g_part2[((size_t)p*BH + bh)*Lq + lb] = make_float2(mx1, sm1);
        }
    }

    // ---- csum1 epilogue: first 128 blocks compute V chunk sums ----
    int mbid = blockIdx.x + NP*blockIdx.y + NP*BH*blockIdx.z;
    if (mbid < (NCH*BH)/16) {
        int gcid = mbid*16 + (tid >> 6);
        int d = tid & 63;
        int cbh = gcid >> 6, ch = gcid & (NCH-1);
        const float* v = V + ((size_t)cbh*Lq + ch*CHLEN)*Dq + d;
        float a = 0.f;
        #pragma unroll
        for (int l = 0; l < CHLEN; l += 4) {
            float x0 = v[(size_t)l*Dq],     x1 = v[(size_t)(l+1)*Dq];
            float x2 = v[(size_t)(l+2)*Dq], x3 = v[(size_t)(l+3)*Dq];
            a += (x0+x1) + (x2+x3);
        }
        g_csum[(cbh*NCH + ch)*Dq + d] = a;
    }
}

// ---------------------------------------------------------------------------
// k_topk: radix-select top-40; digit selection via parallel reversed scan.
// Result sorted desc by row index; also zeroes g_den for this bh.
// ---------------------------------------------------------------------------
__global__ void k_topk() {
    int bh = blockIdx.x, tid = threadIdx.x, lane = tid & 31, wid = tid >> 5;
    __shared__ unsigned keys[Lq];
    __shared__ int hist[256];
    __shared__ int rh[256];
    __shared__ int wsc[8];
    __shared__ int tie[Lq];
    __shared__ int tops[NT];
    __shared__ int sorted[NT];
    __shared__ int s_d, s_acc, s_ngt, s_ntie;

    for (int i = tid; i < Lq; i += 256) {
        float mx = -INFINITY, sm = 0.f;
        #pragma unroll
        for (int p = 0; p < NP; ++p) {
            float2 v = g_part2[((size_t)p*BH + bh)*Lq + i];
            mx = fmaxf(mx, v.x); sm += v.y;
        }
        float m = mx - sm * (1.0f/(float)Lq);
        unsigned u = __float_as_uint(m);
        keys[i] = (u & 0x80000000u) ? ~u : (u | 0x80000000u);
    }
    if (tid == 0) { s_ngt = 0; s_ntie = 0; }
    __syncthreads();

    unsigned prefix = 0; int k = NT;
    #pragma unroll
    for (int level = 3; level >= 0; --level) {
        int sh = level*8;
        hist[tid] = 0;
        __syncthreads();
        unsigned maskAbove = (level==3) ? 0u : (0xFFFFFFFFu << (sh+8));
        for (int i = tid; i < Lq; i += 256) {
            unsigned key = keys[i];
            if ((key & maskAbove) == prefix)
                atomicAdd(&hist[(key >> sh) & 255], 1);
        }
        __syncthreads();
        // reversed inclusive scan: x = sum of hist over digits >= (255-tid)
        rh[tid] = hist[255 - tid];
        __syncthreads();
        int hv = rh[tid];
        int x = hv;
        #pragma unroll
        for (int o = 1; o < 32; o <<= 1) {
            int t = __shfl_up_sync(0xffffffffu, x, o);
            if (lane >= o) x += t;
        }
        if (lane == 31) wsc[wid] = x;
        __syncthreads();
        if (wid == 0 && lane < 8) {
            int y = wsc[lane], inc = y;
            #pragma unroll
            for (int o = 1; o < 8; o <<= 1) {
                int t = __shfl_up_sync(0xffu, inc, o);
                if (lane >= o) inc += t;
            }
            wsc[lane] = inc - y;
        }
        __syncthreads();
        x += wsc[wid];
        int above = x - hv;                      // count of keys with digit > d
        if (x >= k && above < k) { s_d = 255 - tid; s_acc = above; }
        __syncthreads();
        k -= s_acc;
        prefix |= ((unsigned)s_d) << sh;
        __syncthreads();
    }
    unsigned T = prefix;

    for (int i = tid; i < Lq; i += 256) {
        unsigned key = keys[i];
        if (key > T)       { int pos = atomicAdd(&s_ngt, 1);  tops[pos] = i; }
        else if (key == T) { int pos = atomicAdd(&s_ntie, 1); tie[pos]  = i; }
    }
    __syncthreads();
    int ngt = s_ngt, ntie = s_ntie;
    if (tid < 32) {
        for (int t = 0; t < k; ++t) {
            long long best = 0x7FFFFFFFFFFFFFFFLL;
            for (int i = tid; i < ntie; i += 32) {
                long long c = ((long long)tie[i] << 32) | (unsigned)i;
                if (c < best) best = c;
            }
            #pragma unroll
            for (int o = 16; o; o >>= 1) {
                long long c = __shfl_xor_sync(0xffffffffu, best, o);
                if (c < best) best = c;
            }
            if (tid == 0) {
                int slot = (int)(best & 0xffffffffu);
                tops[ngt + t] = (int)(best >> 32);
                tie[slot] = 0x7FFFFFFF;
            }
            __syncwarp();
        }
    }
    __syncthreads();

    // rank-sort desc by row index (rows distinct -> unique ranks)
    if (tid < NT) {
        int me = tops[tid], r = 0;
        #pragma unroll
        for (int jj = 0; jj < NT; ++jj) r += (tops[jj] > me);
        sorted[r] = me;
    }
    __syncthreads();
    if (tid < NT) {
        g_top[bh*NT + tid] = sorted[tid];
        g_den[bh*NT + tid] = 0.f;
    }
}

// ---------------------------------------------------------------------------
// k_sav: fused score+exp+AV per (j-tile 128, bh) + cumsum-output epilogue.
// ---------------------------------------------------------------------------
__global__ void __launch_bounds__(256) k_sav(const float* __restrict__ Q,
                                             const float* __restrict__ K,
                                             const float* __restrict__ V,
                                             float* __restrict__ O) {
    extern __shared__ char sm_raw[];
    float4* qs4  = (float4*)(sm_raw + SAV_QS);
    float*  kt   = (float*) (sm_raw + SAV_KT);
    float*  P    = (float*) (sm_raw + SAV_P);
    float*  Vs   = (float*) (sm_raw + SAV_VS);
    int*    mtop = (int*)   (sm_raw + SAV_MT);
    float*  dsum = (float*) (sm_raw + SAV_DS);
    int*    puc  = (int*)   (sm_raw + SAV_UC);

    int jtx = blockIdx.x, bh = blockIdx.y;
    int jt0 = jtx * JT;
    int tid = threadIdx.x, lane = tid & 31;
    int j = tid & (JT-1), half = tid >> 7;

    if (tid < NT) { mtop[tid] = g_top[bh*NT + tid]; dsum[tid] = 0.f; }
    __syncthreads();
    if (tid == 0) {
        int c = 0;
        while (c < NT && mtop[c] >= jt0) ++c;
        *puc = c;
    }

    const float4* Q4 = (const float4*)Q;
    for (int i = tid; i < NT*16; i += 256) {
        int u = i >> 4, d4 = i & 15;
        qs4[i] = Q4[((size_t)bh*Lq + mtop[u])*16 + d4];
    }
    const float4* K4 = (const float4*)K;
    for (int i = tid; i < JT*16; i += 256) {
        int r = i >> 4, c4 = i & 15;
        float4 v = K4[((size_t)bh*Lq + jt0 + r)*16 + c4];
        kt[r*65 + c4*4+0] = v.x; kt[r*65 + c4*4+1] = v.y;
        kt[r*65 + c4*4+2] = v.z; kt[r*65 + c4*4+3] = v.w;
    }
    const float4* V4 = (const float4*)V;
    float4* Vs4 = (float4*)Vs;
    for (int i = tid; i < JT*16; i += 256)
        Vs4[i] = V4[((size_t)bh*Lq + jt0)*16 + i];
    __syncthreads();
    int ucnt = *puc;

    // ---- Phase A: scores -> exp -> smem P (live u only) ----
    float kr[Dq];
    #pragma unroll
    for (int d = 0; d < Dq; ++d) kr[d] = kt[j*65 + d];

    int jg = jt0 + j;
    #pragma unroll 1
    for (int u = half; u < ucnt; u += 2) {
        int m = mtop[u];
        float s = 0.f;
        #pragma unroll
        for (int d4 = 0; d4 < 16; ++d4) {
            float4 qv = qs4[u*16 + d4];
            s += kr[d4*4+0]*qv.x + kr[d4*4+1]*qv.y + kr[d4*4+2]*qv.z + kr[d4*4+3]*qv.w;
        }
        float e = (jg > m) ? 0.f : __expf(s * 0.125f);
        P[u*JT + j] = e;
        float v = e;
        v += __shfl_xor_sync(0xffffffffu, v, 1);
        v += __shfl_xor_sync(0xffffffffu, v, 2);
        v += __shfl_xor_sync(0xffffffffu, v, 4);
        v += __shfl_xor_sync(0xffffffffu, v, 8);
        v += __shfl_xor_sync(0xffffffffu, v, 16);
        if (lane == 0) atomicAdd(&dsum[u], v);
    }
    __syncthreads();
    if (tid < NT) atomicAdd(&g_den[bh*NT + tid], dsum[tid]);

    // ---- Phase B: AV partials from smem P + smem V ----
    int d = tid & 63, ug = tid >> 6;
    const float4* P4 = (const float4*)P;
    float acc[10];
    #pragma unroll
    for (int k = 0; k < 10; ++k) acc[k] = 0.f;

    #pragma unroll 1
    for (int j4 = 0; j4 < JT/4; ++j4) {
        float v0 = Vs[(j4*4+0)*Dq + d], v1 = Vs[(j4*4+1)*Dq + d];
        float v2 = Vs[(j4*4+2)*Dq + d], v3 = Vs[(j4*4+3)*Dq + d];
        #pragma unroll
        for (int k = 0; k < 10; ++k) {
            int u = ug*10 + k;
            if (u < ucnt) {
                float4 pv = P4[u*(JT/4) + j4];
                acc[k] += pv.x*v0 + pv.y*v1 + pv.z*v2 + pv.w*v3;
            }
        }
    }
    #pragma unroll
    for (int k = 0; k < 10; ++k)
        g_part[(((size_t)bh*NJT + jtx)*NT + ug*10 + k)*Dq + d] = acc[k];

    // ---- Epilogue: cumsum output for one chunk-group (no scatter) ----
    {
        int sbid = jtx + NJT*bh;                 // [0, 512)
        int cbh = sbid >> 4;
        int ch = (sbid & 15)*4 + (tid >> 6);
        int dd = tid & 63;
        float a = 0.f;
        int c = 0;
        for (; c + 4 <= ch; c += 4) {
            float x0 = g_csum[(cbh*NCH + c+0)*Dq + dd];
            float x1 = g_csum[(cbh*NCH + c+1)*Dq + dd];
            float x2 = g_csum[(cbh*NCH + c+2)*Dq + dd];
            float x3 = g_csum[(cbh*NCH + c+3)*Dq + dd];
            a += (x0+x1) + (x2+x3);
        }
        for (; c < ch; ++c) a += g_csum[(cbh*NCH + c)*Dq + dd];

        size_t base = ((size_t)cbh*Lq + ch*CHLEN)*Dq + dd;
        #pragma unroll 4
        for (int l = 0; l < CHLEN; ++l) {
            a += V[base + (size_t)l*Dq];
            O[base + (size_t)l*Dq] = a;
        }
    }
}

// ---------------------------------------------------------------------------
// k_fix: overwrite the 40 selected rows per bh with normalized attention.
// ---------------------------------------------------------------------------
__global__ void k_fix(float* __restrict__ O) {
    int bh = blockIdx.x, tid = threadIdx.x;
    for (int i = tid; i < NT*Dq; i += 256) {
        int u = i >> 6, d = i & 63;
        int row = g_top[bh*NT + u];
        float acc = 0.f;
        #pragma unroll
        for (int js = 0; js < NJT; ++js)
            acc += g_part[(((size_t)bh*NJT + js)*NT + u)*Dq + d];
        O[((size_t)bh*Lq + row)*Dq + d] = acc / g_den[bh*NT + u];
    }
}

extern "C" void kernel_launch(void* const* d_in, const int* in_sizes, int n_in,
                              void* d_out, int out_size) {
    const float* Q = (const float*)d_in[0];
    const float* K = (const float*)d_in[1];
    const float* V = (const float*)d_in[2];
    const int*   I = (const int*)  d_in[3];
    float* O = (float*)d_out;

    cudaFuncSetAttribute(k_M2,  cudaFuncAttributeMaxDynamicSharedMemorySize, SMEM_M2);
    cudaFuncSetAttribute(k_sav, cudaFuncAttributeMaxDynamicSharedMemorySize, SMEM_SAV);

    k_prep <<<NP, 1024>>>(I);
    k_M2   <<<dim3(NP, BH, ZSP), 1024, SMEM_M2>>>(Q, K, V);
    k_topk <<<BH, 256>>>();
    k_sav  <<<dim3(NJT, BH), 256, SMEM_SAV>>>(Q, K, V, O);
    k_fix  <<<BH, 256>>>(O);
}

// round 14
// speedup vs baseline: 1.1300x; 1.1300x over previous
#include <cuda_runtime.h>
#include <math.h>

// B,H,L,D = 4,8,2048,64 ; FACTOR=5 -> sample_k = n_top = 40
#define Bq    4
#define Hq    8
#define Lq    2048
#define Dq    64
#define BH    (Bq*Hq)
#define SK    40
#define NT    40
#define NP    4            // K slices for k_M2
#define SL    (Lq/NP)      // 512 rows per slice
#define ZSP   4            // l-splits per (p,bh) in k_M2
#define ZL    (Lq/ZSP)     // 512 queries per z
#define LMAX  (ZL*SK)      // staged list worst case
#define NCH   64           // cumsum chunks
#define CHLEN (Lq/NCH)     // 32
#define NJT   16           // j-tiles (of 128) for fused score+AV
#define JT    (Lq/NJT)     // 128
#define SMEM_M2  (SL*Dq*4 + (ZL+1+3)*4 + LMAX*4)
// sav smem (bytes): qs4 | kt (reused as Vs in phase B) | P | mtop | dsum | ucnt
#define SAV_QS   0
#define SAV_KT   (SAV_QS + NT*16*16)        // 10240
#define SAV_P    (SAV_KT + JT*65*4)         // 43520
#define SAV_MT   (SAV_P  + NT*JT*4)         // 64000
#define SAV_DS   (SAV_MT + NT*4)            // 64160
#define SAV_UC   (SAV_DS + NT*4)            // 64320
#define SMEM_SAV (SAV_UC + 64)              // 64384

// ---- device scratch (no allocations allowed) ----
__device__ int    g_cnt[NP][Lq];
__device__ int    g_off[NP][Lq+1];     // per-slice offsets (zero-based)
__device__ int    g_list[NP][Lq*SK];   // per-slice sample lists
__device__ float2 g_part2[NP*BH*Lq];
__device__ int    g_top[BH*NT];        // sorted desc by row index
__device__ float  g_den[BH*NT];
__device__ float  g_part[BH*NJT*NT*Dq];
__device__ float  g_csum[BH*NCH*Dq];

// ---------------------------------------------------------------------------
// Prep 1: per-query per-slice counts; zero g_den.
// ---------------------------------------------------------------------------
__global__ void k_cnt(const int* __restrict__ I) {
    int l = blockIdx.x*256 + threadIdx.x;          // grid 8
    if (l < BH*NT) g_den[l] = 0.f;
    int c0=0,c1=0,c2=0,c3=0;
    const int* r = I + l*SK;
    #pragma unroll
    for (int s = 0; s < SK; ++s) {
        int p = r[s] >> 9;
        c0 += (p==0); c1 += (p==1); c2 += (p==2); c3 += (p==3);
    }
    g_cnt[0][l]=c0; g_cnt[1][l]=c1; g_cnt[2][l]=c2; g_cnt[3][l]=c3;
}

// Prep 2: per-slice exclusive prefix (grid NP, zero-based per slice)
__global__ void k_scan() {
    __shared__ int wsum[8];
    int p = blockIdx.x;
    int tid = threadIdx.x, lane = tid & 31, wid = tid >> 5;
    int loc[8]; int s = 0;
    #pragma unroll
    for (int k = 0; k < 8; ++k) { loc[k] = s; s += g_cnt[p][tid*8+k]; }
    int v = s;
    #pragma unroll
    for (int o = 1; o < 32; o <<= 1) {
        int t = __shfl_up_sync(0xffffffffu, v, o);
        if (lane >= o) v += t;
    }
    if (lane == 31) wsum[wid] = v;
    __syncthreads();
    if (tid == 0) {
        int a = 0;
        #pragma unroll
        for (int i = 0; i < 8; ++i) { int t = wsum[i]; wsum[i] = a; a += t; }
    }
    __syncthreads();
    int excl = v - s + wsum[wid];
    #pragma unroll
    for (int k = 0; k < 8; ++k) g_off[p][tid*8+k] = excl + loc[k];
    if (tid == 255) g_off[p][Lq] = excl + s;
}

// Prep 3: fill per-slice lists (local row index within slice)
__global__ void k_fill(const int* __restrict__ I) {
    int l = blockIdx.x*256 + threadIdx.x;
    int o0=g_off[0][l], o1=g_off[1][l], o2=g_off[2][l], o3=g_off[3][l];
    const int* r = I + l*SK;
    #pragma unroll
    for (int s = 0; s < SK; ++s) {
        int j = r[s];
        int p = j >> 9, jj = j & (SL-1);
        if      (p==0) g_list[0][o0++] = jj;
        else if (p==1) g_list[1][o1++] = jj;
        else if (p==2) g_list[2][o2++] = jj;
        else           g_list[3][o3++] = jj;
    }
}

// ---------------------------------------------------------------------------
// k_M2: proven config + csum1 epilogue on the first 128 blocks.
// ---------------------------------------------------------------------------
__global__ void __launch_bounds__(1024) k_M2(const float* __restrict__ Q,
                                             const float* __restrict__ K,
                                             const float* __restrict__ V) {
    extern __shared__ float ks[];
    float4* ks4 = (float4*)ks;
    int* so = (int*)(ks + SL*Dq);
    int* sl = so + (ZL+1+3);
    int p = blockIdx.x, bh = blockIdx.y, z = blockIdx.z;
    int tid = threadIdx.x, warp = tid >> 5, lane = tid & 31;
    int g = lane >> 3, e = lane & 7;
    int zl0 = z*ZL;

    const float4* Ks = (const float4*)(K + ((size_t)bh*Lq + (size_t)p*SL)*Dq);
    for (int i = tid; i < SL*(Dq/4); i += 1024) ks4[i] = Ks[i];

    int sbeg = g_off[p][zl0];
    int send = g_off[p][zl0 + ZL];
    for (int i = tid; i <= ZL; i += 1024) so[i] = g_off[p][zl0 + i] - sbeg;
    for (int i = tid; i < send - sbeg; i += 1024) sl[i] = g_list[p][sbeg + i];
    __syncthreads();

    const float4* Q4 = (const float4*)Q;
    int l0 = zl0 + warp;
    #pragma unroll 1
    for (int i = 0; i < 16; i += 2) {
        int la = l0 + 32*i, lb = la + 32;
        int lla = warp + 32*i, llb = lla + 32;
        int a0 = so[lla], a1 = so[lla+1];
        int b0 = so[llb], b1 = so[llb+1];
        size_t qra = ((size_t)bh*Lq + la)*16;
        size_t qrb = ((size_t)bh*Lq + lb)*16;
        float4 qa0 = Q4[qra + e], qa1 = Q4[qra + e + 8];
        float4 qb0 = Q4[qrb + e], qb1 = Q4[qrb + e + 8];
        float mx0 = -INFINITY, sm0 = 0.f, mx1 = -INFINITY, sm1 = 0.f;
        int c0 = a0, c1 = b0;
        while (c0 < a1 || c1 < b1) {
            float pr0 = 0.f, pr1 = 0.f;
            bool v0 = false, v1 = false;
            if (c0 < a1) {
                int idx = c0 + g; v0 = idx < a1;
                int j = sl[v0 ? idx : a0];
                const float4* kb = ks4 + (j << 4);
                float4 x = kb[e], y = kb[e + 8];
                pr0 = qa0.x*x.x + qa0.y*x.y + qa0.z*x.z + qa0.w*x.w
                    + qa1.x*y.x + qa1.y*y.y + qa1.z*y.z + qa1.w*y.w;
            }
            if (c1 < b1) {
                int idx = c1 + g; v1 = idx < b1;
                int j = sl[v1 ? idx : b0];
                const float4* kb = ks4 + (j << 4);
                float4 x = kb[e], y = kb[e + 8];
                pr1 = qb0.x*x.x + qb0.y*x.y + qb0.z*x.z + qb0.w*x.w
                    + qb1.x*y.x + qb1.y*y.y + qb1.z*y.z + qb1.w*y.w;
            }
            pr0 += __shfl_xor_sync(0xffffffffu, pr0, 1);
            pr1 += __shfl_xor_sync(0xffffffffu, pr1, 1);
            pr0 += __shfl_xor_sync(0xffffffffu, pr0, 2);
            pr1 += __shfl_xor_sync(0xffffffffu, pr1, 2);
            pr0 += __shfl_xor_sync(0xffffffffu, pr0, 4);
            pr1 += __shfl_xor_sync(0xffffffffu, pr1, 4);
            if (v0) { mx0 = fmaxf(mx0, pr0); sm0 += pr0; }
            if (v1) { mx1 = fmaxf(mx1, pr1); sm1 += pr1; }
            c0 += 4; c1 += 4;
        }
        mx0 = fmaxf(mx0, __shfl_xor_sync(0xffffffffu, mx0, 8));
        mx0 = fmaxf(mx0, __shfl_xor_sync(0xffffffffu, mx0, 16));
        sm0 += __shfl_xor_sync(0xffffffffu, sm0, 8);
        sm0 += __shfl_xor_sync(0xffffffffu, sm0, 16);
        mx1 = fmaxf(mx1, __shfl_xor_sync(0xffffffffu, mx1, 8));
        mx1 = fmaxf(mx1, __shfl_xor_sync(0xffffffffu, mx1, 16));
        sm1 += __shfl_xor_sync(0xffffffffu, sm1, 8);
        sm1 += __shfl_xor_sync(0xffffffffu, sm1, 16);
        if (lane == 0) {
            g_part2[((size_t)p*BH + bh)*Lq + la] = make_float2(mx0, sm0);
            g_part2[((size_t)p*BH + bh)*Lq + lb] = make_float2(mx1, sm1);
        }
    }

    // ---- csum1 epilogue: first 128 blocks compute V chunk sums ----
    int mbid = blockIdx.x + NP*blockIdx.y + NP*BH*blockIdx.z;
    if (mbid < (NCH*BH)/16) {
        int gcid = mbid*16 + (tid >> 6);
        int d = tid & 63;
        int cbh = gcid >> 6, ch = gcid & (NCH-1);
        const float* v = V + ((size_t)cbh*Lq + ch*CHLEN)*Dq + d;
        float a = 0.f;
        #pragma unroll
        for (int l = 0; l < CHLEN; l += 4) {
            float x0 = v[(size_t)l*Dq],     x1 = v[(size_t)(l+1)*Dq];
            float x2 = v[(size_t)(l+2)*Dq], x3 = v[(size_t)(l+3)*Dq];
            a += (x0+x1) + (x2+x3);
        }
        g_csum[(cbh*NCH + ch)*Dq + d] = a;
    }
}

// ---------------------------------------------------------------------------
// k_topk (R12-proven): radix-select top-40, serial digit walk; rank-sort desc.
// ---------------------------------------------------------------------------
__global__ void k_topk() {
    int bh = blockIdx.x, tid = threadIdx.x;
    __shared__ unsigned keys[Lq];
    __shared__ int hist[256];
    __shared__ int tie[Lq];
    __shared__ int tops[NT];
    __shared__ int sorted[NT];
    __shared__ int s_d, s_acc, s_ngt, s_ntie;

    for (int i = tid; i < Lq; i += 256) {
        float mx = -INFINITY, sm = 0.f;
        #pragma unroll
        for (int p = 0; p < NP; ++p) {
            float2 v = g_part2[((size_t)p*BH + bh)*Lq + i];
            mx = fmaxf(mx, v.x); sm += v.y;
        }
        float m = mx - sm * (1.0f/(float)Lq);
        unsigned u = __float_as_uint(m);
        keys[i] = (u & 0x80000000u) ? ~u : (u | 0x80000000u);
    }
    if (tid == 0) { s_ngt = 0; s_ntie = 0; }
    __syncthreads();

    unsigned prefix = 0; int k = NT;
    #pragma unroll
    for (int level = 3; level >= 0; --level) {
        int sh = level*8;
        hist[tid] = 0;
        __syncthreads();
        unsigned maskAbove = (level==3) ? 0u : (0xFFFFFFFFu << (sh+8));
        for (int i = tid; i < Lq; i += 256) {
            unsigned key = keys[i];
            if ((key & maskAbove) == prefix)
                atomicAdd(&hist[(key >> sh) & 255], 1);
        }
        __syncthreads();
        if (tid == 0) {
            int acc = 0, d = 255;
            for (; d > 0; --d) { if (acc + hist[d] >= k) break; acc += hist[d]; }
            s_d = d; s_acc = acc;
        }
        __syncthreads();
        k -= s_acc;
        prefix |= ((unsigned)s_d) << sh;
        __syncthreads();
    }
    unsigned T = prefix;

    for (int i = tid; i < Lq; i += 256) {
        unsigned key = keys[i];
        if (key > T)       { int pos = atomicAdd(&s_ngt, 1);  tops[pos] = i; }
        else if (key == T) { int pos = atomicAdd(&s_ntie, 1); tie[pos]  = i; }
    }
    __syncthreads();
    int ngt = s_ngt, ntie = s_ntie;
    if (tid < 32) {
        for (int t = 0; t < k; ++t) {
            long long best = 0x7FFFFFFFFFFFFFFFLL;
            for (int i = tid; i < ntie; i += 32) {
                long long c = ((long long)tie[i] << 32) | (unsigned)i;
                if (c < best) best = c;
            }
            #pragma unroll
            for (int o = 16; o; o >>= 1) {
                long long c = __shfl_xor_sync(0xffffffffu, best, o);
                if (c < best) best = c;
            }
            if (tid == 0) {
                int slot = (int)(best & 0xffffffffu);
                tops[ngt + t] = (int)(best >> 32);
                tie[slot] = 0x7FFFFFFF;
            }
            __syncwarp();
        }
    }
    __syncthreads();

    // rank-sort desc by row index (rows distinct -> unique ranks)
    if (tid < NT) {
        int me = tops[tid], r = 0;
        #pragma unroll
        for (int jj = 0; jj < NT; ++jj) r += (tops[jj] > me);
        sorted[r] = me;
    }
    __syncthreads();
    if (tid < NT) g_top[bh*NT + tid] = sorted[tid];
}

// ---------------------------------------------------------------------------
// k_sav: fused score+exp+AV per (j-tile 128, bh). K tile smem is DEAD after
// kr-register extraction -> reuse those bytes for the V tile (smem 97->64KB,
// 3 CTAs/SM). Epilogue: cumsum output for one chunk-group.
// ---------------------------------------------------------------------------
__global__ void __launch_bounds__(256, 3) k_sav(const float* __restrict__ Q,
                                                const float* __restrict__ K,
                                                const float* __restrict__ V,
                                                float* __restrict__ O) {
    extern __shared__ char sm_raw[];
    float4* qs4  = (float4*)(sm_raw + SAV_QS);
    float*  kt   = (float*) (sm_raw + SAV_KT);   // K tile, then V tile
    float*  P    = (float*) (sm_raw + SAV_P);
    int*    mtop = (int*)   (sm_raw + SAV_MT);
    float*  dsum = (float*) (sm_raw + SAV_DS);
    int*    puc  = (int*)   (sm_raw + SAV_UC);

    int jtx = blockIdx.x, bh = blockIdx.y;
    int jt0 = jtx * JT;
    int tid = threadIdx.x, lane = tid & 31;
    int j = tid & (JT-1), half = tid >> 7;

    if (tid < NT) { mtop[tid] = g_top[bh*NT + tid]; dsum[tid] = 0.f; }
    __syncthreads();
    if (tid == 0) {
        int c = 0;
        while (c < NT && mtop[c] >= jt0) ++c;
        *puc = c;
    }

    const float4* Q4 = (const float4*)Q;
    for (int i = tid; i < NT*16; i += 256) {
        int u = i >> 4, d4 = i & 15;
        qs4[i] = Q4[((size_t)bh*Lq + mtop[u])*16 + d4];
    }
    const float4* K4 = (const float4*)K;
    for (int i = tid; i < JT*16; i += 256) {
        int r = i >> 4, c4 = i & 15;
        float4 v = K4[((size_t)bh*Lq + jt0 + r)*16 + c4];
        kt[r*65 + c4*4+0] = v.x; kt[r*65 + c4*4+1] = v.y;
        kt[r*65 + c4*4+2] = v.z; kt[r*65 + c4*4+3] = v.w;
    }
    __syncthreads();
    int ucnt = *puc;

    // extract K row into registers; kt bytes are dead afterwards
    float kr[Dq];
    #pragma unroll
    for (int d = 0; d < Dq; ++d) kr[d] = kt[j*65 + d];
    __syncthreads();                       // everyone done reading kt

    // stage V tile into the former kt bytes (overlaps with phase A compute)
    float* Vs = kt;                        // [JT][Dq] row-major
    float4* Vs4 = (float4*)Vs;
    const float4* V4 = (const float4*)V;
    for (int i = tid; i < JT*16; i += 256)
        Vs4[i] = V4[((size_t)bh*Lq + jt0)*16 + i];

    // ---- Phase A: scores -> exp -> smem P (live u only) ----
    int jg = jt0 + j;
    #pragma unroll 1
    for (int u = half; u < ucnt; u += 2) {
        int m = mtop[u];
        float s = 0.f;
        #pragma unroll
        for (int d4 = 0; d4 < 16; ++d4) {
            float4 qv = qs4[u*16 + d4];
            s += kr[d4*4+0]*qv.x + kr[d4*4+1]*qv.y + kr[d4*4+2]*qv.z + kr[d4*4+3]*qv.w;
        }
        float e = (jg > m) ? 0.f : __expf(s * 0.125f);
        P[u*JT + j] = e;
        float v = e;
        v += __shfl_xor_sync(0xffffffffu, v, 1);
        v += __shfl_xor_sync(0xffffffffu, v, 2);
        v += __shfl_xor_sync(0xffffffffu, v, 4);
        v += __shfl_xor_sync(0xffffffffu, v, 8);
        v += __shfl_xor_sync(0xffffffffu, v, 16);
        if (lane == 0) atomicAdd(&dsum[u], v);
    }
    __syncthreads();                       // P + Vs both ready
    if (tid < NT) atomicAdd(&g_den[bh*NT + tid], dsum[tid]);

    // ---- Phase B: AV partials from smem P + smem Vs ----
    int d = tid & 63, ug = tid >> 6;
    const float4* P4 = (const float4*)P;
    float acc[10];
    #pragma unroll
    for (int k = 0; k < 10; ++k) acc[k] = 0.f;

    #pragma unroll 1
    for (int j4 = 0; j4 < JT/4; ++j4) {
        float v0 = Vs[(j4*4+0)*Dq + d], v1 = Vs[(j4*4+1)*Dq + d];
        float v2 = Vs[(j4*4+2)*Dq + d], v3 = Vs[(j4*4+3)*Dq + d];
        #pragma unroll
        for (int k = 0; k < 10; ++k) {
            int u = ug*10 + k;
            if (u < ucnt) {
                float4 pv = P4[u*(JT/4) + j4];
                acc[k] += pv.x*v0 + pv.y*v1 + pv.z*v2 + pv.w*v3;
            }
        }
    }
    #pragma unroll
    for (int k = 0; k < 10; ++k)
        g_part[(((size_t)bh*NJT + jtx)*NT + ug*10 + k)*Dq + d] = acc[k];

    // ---- Epilogue: cumsum output for one chunk-group (no scatter) ----
    {
        int sbid = jtx + NJT*bh;                 // [0, 512)
        int cbh = sbid >> 4;
        int ch = (sbid & 15)*4 + (tid >> 6);
        int dd = tid & 63;
        float a = 0.f;
        int c = 0;
        for (; c + 4 <= ch; c += 4) {
            float x0 = g_csum[(cbh*NCH + c+0)*Dq + dd];
            float x1 = g_csum[(cbh*NCH + c+1)*Dq + dd];
            float x2 = g_csum[(cbh*NCH + c+2)*Dq + dd];
            float x3 = g_csum[(cbh*NCH + c+3)*Dq + dd];
            a += (x0+x1) + (x2+x3);
        }
        for (; c < ch; ++c) a += g_csum[(cbh*NCH + c)*Dq + dd];

        size_t base = ((size_t)cbh*Lq + ch*CHLEN)*Dq + dd;
        #pragma unroll 4
        for (int l = 0; l < CHLEN; ++l) {
            a += V[base + (size_t)l*Dq];
            O[base + (size_t)l*Dq] = a;
        }
    }
}

// ---------------------------------------------------------------------------
// k_fix: overwrite the 40 selected rows per bh with normalized attention.
// ---------------------------------------------------------------------------
__global__ void k_fix(float* __restrict__ O) {
    int bh = blockIdx.x, tid = threadIdx.x;
    for (int i = tid; i < NT*Dq; i += 256) {
        int u = i >> 6, d = i & 63;
        int row = g_top[bh*NT + u];
        float acc = 0.f;
        #pragma unroll
        for (int js = 0; js < NJT; ++js)
            acc += g_part[(((size_t)bh*NJT + js)*NT + u)*Dq + d];
        O[((size_t)bh*Lq + row)*Dq + d] = acc / g_den[bh*NT + u];
    }
}

extern "C" void kernel_launch(void* const* d_in, const int* in_sizes, int n_in,
                              void* d_out, int out_size) {
    const float* Q = (const float*)d_in[0];
    const float* K = (const float*)d_in[1];
    const float* V = (const float*)d_in[2];
    const int*   I = (const int*)  d_in[3];
    float* O = (float*)d_out;

    cudaFuncSetAttribute(k_M2,  cudaFuncAttributeMaxDynamicSharedMemorySize, SMEM_M2);
    cudaFuncSetAttribute(k_sav, cudaFuncAttributeMaxDynamicSharedMemorySize, SMEM_SAV);

    k_cnt  <<<Lq/256, 256>>>(I);
    k_scan <<<NP, 256>>>();
    k_fill <<<Lq/256, 256>>>(I);
    k_M2   <<<dim3(NP, BH, ZSP), 1024, SMEM_M2>>>(Q, K, V);
    k_topk <<<BH, 256>>>();
    k_sav  <<<dim3(NJT, BH), 256, SMEM_SAV>>>(Q, K, V, O);
    k_fix  <<<BH, 256>>>(O);
}

// round 15
// speedup vs baseline: 1.1571x; 1.0240x over previous
#include <cuda_runtime.h>
#include <math.h>

// B,H,L,D = 4,8,2048,64 ; FACTOR=5 -> sample_k = n_top = 40
#define Bq    4
#define Hq    8
#define Lq    2048
#define Dq    64
#define BH    (Bq*Hq)
#define SK    40
#define NT    40
#define NP    4            // K slices for k_M2
#define SL    (Lq/NP)      // 512 rows per slice
#define ZSP   4            // l-splits per (p,bh) in k_M2
#define ZL    (Lq/ZSP)     // 512 queries per z
#define LMAX  (ZL*SK)      // staged list worst case
#define NCH   64           // cumsum chunks
#define CHLEN (Lq/NCH)     // 32
#define NJT   16           // j-tiles (of 128) for fused score+AV
#define JT    (Lq/NJT)     // 128
#define SMEM_M2  (SL*Dq*4 + (ZL+1+3)*4 + LMAX*4)
// sav smem (bytes): qs4 | kt (reused as Vs in phase B) | P | mtop | dsum | ucnt
#define SAV_QS   0
#define SAV_KT   (SAV_QS + NT*16*16)        // 10240
#define SAV_P    (SAV_KT + JT*65*4)         // 43520
#define SAV_MT   (SAV_P  + NT*JT*4)         // 64000
#define SAV_DS   (SAV_MT + NT*4)            // 64160
#define SAV_UC   (SAV_DS + NT*4)            // 64320
#define SMEM_SAV (SAV_UC + 64)              // 64384

// ---- device scratch (no allocations allowed) ----
__device__ int    g_cnt[NP][Lq];
__device__ int    g_off[NP][Lq+1];     // per-slice offsets (zero-based)
__device__ int    g_list[NP][Lq*SK];   // per-slice sample lists
__device__ float2 g_part2[NP*BH*Lq];
__device__ int    g_top[BH*NT];        // sorted desc by row index
__device__ float  g_den[BH*NT];
__device__ float  g_part[BH*NJT*NT*Dq];
__device__ float  g_csum[BH*NCH*Dq];
__device__ int    g_ctr1[BH];          // k_M2 tail-election counters
__device__ int    g_ctr2[BH];          // k_sav tail-election counters

// ---------------------------------------------------------------------------
// Prep 1: counts; zero g_den and the tail counters (per-launch determinism).
// ---------------------------------------------------------------------------
__global__ void k_cnt(const int* __restrict__ I) {
    int l = blockIdx.x*256 + threadIdx.x;          // grid 8
    if (l < BH*NT) g_den[l] = 0.f;
    if (l < BH) { g_ctr1[l] = 0; g_ctr2[l] = 0; }
    int c0=0,c1=0,c2=0,c3=0;
    const int* r = I + l*SK;
    #pragma unroll
    for (int s = 0; s < SK; ++s) {
        int p = r[s] >> 9;
        c0 += (p==0); c1 += (p==1); c2 += (p==2); c3 += (p==3);
    }
    g_cnt[0][l]=c0; g_cnt[1][l]=c1; g_cnt[2][l]=c2; g_cnt[3][l]=c3;
}

// Prep 2: per-slice exclusive prefix (grid NP)
__global__ void k_scan() {
    __shared__ int wsum[8];
    int p = blockIdx.x;
    int tid = threadIdx.x, lane = tid & 31, wid = tid >> 5;
    int loc[8]; int s = 0;
    #pragma unroll
    for (int k = 0; k < 8; ++k) { loc[k] = s; s += g_cnt[p][tid*8+k]; }
    int v = s;
    #pragma unroll
    for (int o = 1; o < 32; o <<= 1) {
        int t = __shfl_up_sync(0xffffffffu, v, o);
        if (lane >= o) v += t;
    }
    if (lane == 31) wsum[wid] = v;
    __syncthreads();
    if (tid == 0) {
        int a = 0;
        #pragma unroll
        for (int i = 0; i < 8; ++i) { int t = wsum[i]; wsum[i] = a; a += t; }
    }
    __syncthreads();
    int excl = v - s + wsum[wid];
    #pragma unroll
    for (int k = 0; k < 8; ++k) g_off[p][tid*8+k] = excl + loc[k];
    if (tid == 255) g_off[p][Lq] = excl + s;
}

// Prep 3: fill per-slice lists
__global__ void k_fill(const int* __restrict__ I) {
    int l = blockIdx.x*256 + threadIdx.x;
    int o0=g_off[0][l], o1=g_off[1][l], o2=g_off[2][l], o3=g_off[3][l];
    const int* r = I + l*SK;
    #pragma unroll
    for (int s = 0; s < SK; ++s) {
        int j = r[s];
        int p = j >> 9, jj = j & (SL-1);
        if      (p==0) g_list[0][o0++] = jj;
        else if (p==1) g_list[1][o1++] = jj;
        else if (p==2) g_list[2][o2++] = jj;
        else           g_list[3][o3++] = jj;
    }
}

// ---------------------------------------------------------------------------
// k_M2: proven core + csum1 epilogue + LAST-BLOCK-PER-BH runs the top-40
// radix select (keys/tie reuse the dead K-slice smem).
// ---------------------------------------------------------------------------
__global__ void __launch_bounds__(1024) k_M2(const float* __restrict__ Q,
                                             const float* __restrict__ K,
                                             const float* __restrict__ V) {
    extern __shared__ float ks[];
    float4* ks4 = (float4*)ks;
    int* so = (int*)(ks + SL*Dq);
    int* sl = so + (ZL+1+3);
    int p = blockIdx.x, bh = blockIdx.y, z = blockIdx.z;
    int tid = threadIdx.x, warp = tid >> 5, lane = tid & 31;
    int g = lane >> 3, e = lane & 7;
    int zl0 = z*ZL;

    const float4* Ks = (const float4*)(K + ((size_t)bh*Lq + (size_t)p*SL)*Dq);
    for (int i = tid; i < SL*(Dq/4); i += 1024) ks4[i] = Ks[i];

    int sbeg = g_off[p][zl0];
    int send = g_off[p][zl0 + ZL];
    for (int i = tid; i <= ZL; i += 1024) so[i] = g_off[p][zl0 + i] - sbeg;
    for (int i = tid; i < send - sbeg; i += 1024) sl[i] = g_list[p][sbeg + i];
    __syncthreads();

    const float4* Q4 = (const float4*)Q;
    int l0 = zl0 + warp;
    #pragma unroll 1
    for (int i = 0; i < 16; i += 2) {
        int la = l0 + 32*i, lb = la + 32;
        int lla = warp + 32*i, llb = lla + 32;
        int a0 = so[lla], a1 = so[lla+1];
        int b0 = so[llb], b1 = so[llb+1];
        size_t qra = ((size_t)bh*Lq + la)*16;
        size_t qrb = ((size_t)bh*Lq + lb)*16;
        float4 qa0 = Q4[qra + e], qa1 = Q4[qra + e + 8];
        float4 qb0 = Q4[qrb + e], qb1 = Q4[qrb + e + 8];
        float mx0 = -INFINITY, sm0 = 0.f, mx1 = -INFINITY, sm1 = 0.f;
        int c0 = a0, c1 = b0;
        while (c0 < a1 || c1 < b1) {
            float pr0 = 0.f, pr1 = 0.f;
            bool v0 = false, v1 = false;
            if (c0 < a1) {
                int idx = c0 + g; v0 = idx < a1;
                int j = sl[v0 ? idx : a0];
                const float4* kb = ks4 + (j << 4);
                float4 x = kb[e], y = kb[e + 8];
                pr0 = qa0.x*x.x + qa0.y*x.y + qa0.z*x.z + qa0.w*x.w
                    + qa1.x*y.x + qa1.y*y.y + qa1.z*y.z + qa1.w*y.w;
            }
            if (c1 < b1) {
                int idx = c1 + g; v1 = idx < b1;
                int j = sl[v1 ? idx : b0];
                const float4* kb = ks4 + (j << 4);
                float4 x = kb[e], y = kb[e + 8];
                pr1 = qb0.x*x.x + qb0.y*x.y + qb0.z*x.z + qb0.w*x.w
                    + qb1.x*y.x + qb1.y*y.y + qb1.z*y.z + qb1.w*y.w;
            }
            pr0 += __shfl_xor_sync(0xffffffffu, pr0, 1);
            pr1 += __shfl_xor_sync(0xffffffffu, pr1, 1);
            pr0 += __shfl_xor_sync(0xffffffffu, pr0, 2);
            pr1 += __shfl_xor_sync(0xffffffffu, pr1, 2);
            pr0 += __shfl_xor_sync(0xffffffffu, pr0, 4);
            pr1 += __shfl_xor_sync(0xffffffffu, pr1, 4);
            if (v0) { mx0 = fmaxf(mx0, pr0); sm0 += pr0; }
            if (v1) { mx1 = fmaxf(mx1, pr1); sm1 += pr1; }
            c0 += 4; c1 += 4;
        }
        mx0 = fmaxf(mx0, __shfl_xor_sync(0xffffffffu, mx0, 8));
        mx0 = fmaxf(mx0, __shfl_xor_sync(0xffffffffu, mx0, 16));
        sm0 += __shfl_xor_sync(0xffffffffu, sm0, 8);
        sm0 += __shfl_xor_sync(0xffffffffu, sm0, 16);
        mx1 = fmaxf(mx1, __shfl_xor_sync(0xffffffffu, mx1, 8));
        mx1 = fmaxf(mx1, __shfl_xor_sync(0xffffffffu, mx1, 16));
        sm1 += __shfl_xor_sync(0xffffffffu, sm1, 8);
        sm1 += __shfl_xor_sync(0xffffffffu, sm1, 16);
        if (lane == 0) {
            g_part2[((size_t)p*BH + bh)*Lq + la] = make_float2(mx0, sm0);
            g_part2[((size_t)p*BH + bh)*Lq + lb] = make_float2(mx1, sm1);
        }
    }

    // ---- csum1 epilogue: first 128 blocks compute V chunk sums ----
    int mbid = blockIdx.x + NP*blockIdx.y + NP*BH*blockIdx.z;
    if (mbid < (NCH*BH)/16) {
        int gcid = mbid*16 + (tid >> 6);
        int d = tid & 63;
        int cbh = gcid >> 6, ch = gcid & (NCH-1);
        const float* v = V + ((size_t)cbh*Lq + ch*CHLEN)*Dq + d;
        float a = 0.f;
        #pragma unroll
        for (int l = 0; l < CHLEN; l += 4) {
            float x0 = v[(size_t)l*Dq],     x1 = v[(size_t)(l+1)*Dq];
            float x2 = v[(size_t)(l+2)*Dq], x3 = v[(size_t)(l+3)*Dq];
            a += (x0+x1) + (x2+x3);
        }
        g_csum[(cbh*NCH + ch)*Dq + d] = a;
    }

    // ---- tail election: last of the 16 blocks for this bh runs top-40 ----
    __shared__ int s_last;
    __shared__ int hist[256];
    __shared__ int tops[NT];
    __shared__ int sorted[NT];
    __shared__ int s_d, s_acc, s_ngt, s_ntie;
    if (tid == 0) {
        __threadfence();
        int c = atomicAdd(&g_ctr1[bh], 1);
        s_last = (c == NP*ZSP - 1);
    }
    __syncthreads();
    if (!s_last) return;
    __threadfence();                      // acquire all g_part2 writes

    unsigned* keys = (unsigned*)ks;       // reuse dead K-slice smem
    int* tie = (int*)(keys + Lq);

    for (int i = tid; i < Lq; i += 1024) {
        float mx = -INFINITY, sm = 0.f;
        #pragma unroll
        for (int pp = 0; pp < NP; ++pp) {
            float2 v = g_part2[((size_t)pp*BH + bh)*Lq + i];
            mx = fmaxf(mx, v.x); sm += v.y;
        }
        float m = mx - sm * (1.0f/(float)Lq);
        unsigned u = __float_as_uint(m);
        keys[i] = (u & 0x80000000u) ? ~u : (u | 0x80000000u);
    }
    if (tid == 0) { s_ngt = 0; s_ntie = 0; }
    __syncthreads();

    unsigned prefix = 0; int k = NT;
    #pragma unroll
    for (int level = 3; level >= 0; --level) {
        int sh = level*8;
        if (tid < 256) hist[tid] = 0;
        __syncthreads();
        unsigned maskAbove = (level==3) ? 0u : (0xFFFFFFFFu << (sh+8));
        for (int i = tid; i < Lq; i += 1024) {
            unsigned key = keys[i];
            if ((key & maskAbove) == prefix)
                atomicAdd(&hist[(key >> sh) & 255], 1);
        }
        __syncthreads();
        if (tid == 0) {
            int acc = 0, d = 255;
            for (; d > 0; --d) { if (acc + hist[d] >= k) break; acc += hist[d]; }
            s_d = d; s_acc = acc;
        }
        __syncthreads();
        k -= s_acc;
        prefix |= ((unsigned)s_d) << sh;
        __syncthreads();
    }
    unsigned T = prefix;

    for (int i = tid; i < Lq; i += 1024) {
        unsigned key = keys[i];
        if (key > T)       { int pos = atomicAdd(&s_ngt, 1);  tops[pos] = i; }
        else if (key == T) { int pos = atomicAdd(&s_ntie, 1); tie[pos]  = i; }
    }
    __syncthreads();
    int ngt = s_ngt, ntie = s_ntie;
    if (tid < 32) {
        for (int t = 0; t < k; ++t) {
            long long best = 0x7FFFFFFFFFFFFFFFLL;
            for (int i = tid; i < ntie; i += 32) {
                long long c = ((long long)tie[i] << 32) | (unsigned)i;
                if (c < best) best = c;
            }
            #pragma unroll
            for (int o = 16; o; o >>= 1) {
                long long c = __shfl_xor_sync(0xffffffffu, best, o);
                if (c < best) best = c;
            }
            if (tid == 0) {
                int slot = (int)(best & 0xffffffffu);
                tops[ngt + t] = (int)(best >> 32);
                tie[slot] = 0x7FFFFFFF;
            }
            __syncwarp();
        }
    }
    __syncthreads();

    // rank-sort desc by row index (rows distinct -> unique ranks)
    if (tid < NT) {
        int me = tops[tid], r = 0;
        #pragma unroll
        for (int jj = 0; jj < NT; ++jj) r += (tops[jj] > me);
        sorted[r] = me;
    }
    __syncthreads();
    if (tid < NT) g_top[bh*NT + tid] = sorted[tid];
}

// ---------------------------------------------------------------------------
// k_sav: fused score+exp+AV (+cumsum epilogue); LAST block per bh also runs
// the fix (overwrite selected rows with normalized attention).
// ---------------------------------------------------------------------------
__global__ void __launch_bounds__(256, 3) k_sav(const float* __restrict__ Q,
                                                const float* __restrict__ K,
                                                const float* __restrict__ V,
                                                float* __restrict__ O) {
    extern __shared__ char sm_raw[];
    float4* qs4  = (float4*)(sm_raw + SAV_QS);
    float*  kt   = (float*) (sm_raw + SAV_KT);   // K tile, then V tile
    float*  P    = (float*) (sm_raw + SAV_P);
    int*    mtop = (int*)   (sm_raw + SAV_MT);
    float*  dsum = (float*) (sm_raw + SAV_DS);
    int*    puc  = (int*)   (sm_raw + SAV_UC);

    int jtx = blockIdx.x, bh = blockIdx.y;
    int jt0 = jtx * JT;
    int tid = threadIdx.x, lane = tid & 31;
    int j = tid & (JT-1), half = tid >> 7;

    if (tid < NT) { mtop[tid] = g_top[bh*NT + tid]; dsum[tid] = 0.f; }
    __syncthreads();
    if (tid == 0) {
        int c = 0;
        while (c < NT && mtop[c] >= jt0) ++c;
        *puc = c;
    }

    const float4* Q4 = (const float4*)Q;
    for (int i = tid; i < NT*16; i += 256) {
        int u = i >> 4, d4 = i & 15;
        qs4[i] = Q4[((size_t)bh*Lq + mtop[u])*16 + d4];
    }
    const float4* K4 = (const float4*)K;
    for (int i = tid; i < JT*16; i += 256) {
        int r = i >> 4, c4 = i & 15;
        float4 v = K4[((size_t)bh*Lq + jt0 + r)*16 + c4];
        kt[r*65 + c4*4+0] = v.x; kt[r*65 + c4*4+1] = v.y;
        kt[r*65 + c4*4+2] = v.z; kt[r*65 + c4*4+3] = v.w;
    }
    __syncthreads();
    int ucnt = *puc;

    // extract K row into registers; kt bytes are dead afterwards
    float kr[Dq];
    #pragma unroll
    for (int d = 0; d < Dq; ++d) kr[d] = kt[j*65 + d];
    __syncthreads();                       // everyone done reading kt

    // stage V tile into the former kt bytes (overlaps with phase A compute)
    float* Vs = kt;                        // [JT][Dq] row-major
    float4* Vs4 = (float4*)Vs;
    const float4* V4 = (const float4*)V;
    for (int i = tid; i < JT*16; i += 256)
        Vs4[i] = V4[((size_t)bh*Lq + jt0)*16 + i];

    // ---- Phase A: scores -> exp -> smem P (live u only) ----
    int jg = jt0 + j;
    #pragma unroll 1
    for (int u = half; u < ucnt; u += 2) {
        int m = mtop[u];
        float s = 0.f;
        #pragma unroll
        for (int d4 = 0; d4 < 16; ++d4) {
            float4 qv = qs4[u*16 + d4];
            s += kr[d4*4+0]*qv.x + kr[d4*4+1]*qv.y + kr[d4*4+2]*qv.z + kr[d4*4+3]*qv.w;
        }
        float e = (jg > m) ? 0.f : __expf(s * 0.125f);
        P[u*JT + j] = e;
        float v = e;
        v += __shfl_xor_sync(0xffffffffu, v, 1);
        v += __shfl_xor_sync(0xffffffffu, v, 2);
        v += __shfl_xor_sync(0xffffffffu, v, 4);
        v += __shfl_xor_sync(0xffffffffu, v, 8);
        v += __shfl_xor_sync(0xffffffffu, v, 16);
        if (lane == 0) atomicAdd(&dsum[u], v);
    }
    __syncthreads();                       // P + Vs both ready
    if (tid < NT) atomicAdd(&g_den[bh*NT + tid], dsum[tid]);

    // ---- Phase B: AV partials from smem P + smem Vs ----
    int d = tid & 63, ug = tid >> 6;
    const float4* P4 = (const float4*)P;
    float acc[10];
    #pragma unroll
    for (int k = 0; k < 10; ++k) acc[k] = 0.f;

    #pragma unroll 1
    for (int j4 = 0; j4 < JT/4; ++j4) {
        float v0 = Vs[(j4*4+0)*Dq + d], v1 = Vs[(j4*4+1)*Dq + d];
        float v2 = Vs[(j4*4+2)*Dq + d], v3 = Vs[(j4*4+3)*Dq + d];
        #pragma unroll
        for (int k = 0; k < 10; ++k) {
            int u = ug*10 + k;
            if (u < ucnt) {
                float4 pv = P4[u*(JT/4) + j4];
                acc[k] += pv.x*v0 + pv.y*v1 + pv.z*v2 + pv.w*v3;
            }
        }
    }
    #pragma unroll
    for (int k = 0; k < 10; ++k)
        g_part[(((size_t)bh*NJT + jtx)*NT + ug*10 + k)*Dq + d] = acc[k];

    // ---- Epilogue: cumsum output for one chunk-group (no scatter) ----
    {
        int sbid = jtx + NJT*bh;                 // [0, 512)
        int cbh = sbid >> 4;                     // == bh
        int ch = (sbid & 15)*4 + (tid >> 6);
        int dd = tid & 63;
        float a = 0.f;
        int c = 0;
        for (; c + 4 <= ch; c += 4) {
            float x0 = g_csum[(cbh*NCH + c+0)*Dq + dd];
            float x1 = g_csum[(cbh*NCH + c+1)*Dq + dd];
            float x2 = g_csum[(cbh*NCH + c+2)*Dq + dd];
            float x3 = g_csum[(cbh*NCH + c+3)*Dq + dd];
            a += (x0+x1) + (x2+x3);
        }
        for (; c < ch; ++c) a += g_csum[(cbh*NCH + c)*Dq + dd];

        size_t base = ((size_t)cbh*Lq + ch*CHLEN)*Dq + dd;
        #pragma unroll 4
        for (int l = 0; l < CHLEN; ++l) {
            a += V[base + (size_t)l*Dq];
            O[base + (size_t)l*Dq] = a;
        }
    }

    // ---- tail election: last of the 16 blocks for this bh runs the fix ----
    __shared__ int s_last2;
    if (tid == 0) {
        __threadfence();
        int c = atomicAdd(&g_ctr2[bh], 1);
        s_last2 = (c == NJT - 1);
    }
    __syncthreads();
    if (!s_last2) return;
    __threadfence();                       // acquire g_part/g_den/O writes

    for (int i = tid; i < NT*Dq; i += 256) {
        int u = i >> 6, dd = i & 63;
        int row = g_top[bh*NT + u];
        float acc2 = 0.f;
        #pragma unroll
        for (int js = 0; js < NJT; ++js)
            acc2 += g_part[(((size_t)bh*NJT + js)*NT + u)*Dq + dd];
        O[((size_t)bh*Lq + row)*Dq + dd] = acc2 / g_den[bh*NT + u];
    }
}

extern "C" void kernel_launch(void* const* d_in, const int* in_sizes, int n_in,
                              void* d_out, int out_size) {
    const float* Q = (const float*)d_in[0];
    const float* K = (const float*)d_in[1];
    const float* V = (const float*)d_in[2];
    const int*   I = (const int*)  d_in[3];
    float* O = (float*)d_out;

    cudaFuncSetAttribute(k_M2,  cudaFuncAttributeMaxDynamicSharedMemorySize, SMEM_M2);
    cudaFuncSetAttribute(k_sav, cudaFuncAttributeMaxDynamicSharedMemorySize, SMEM_SAV);

    k_cnt  <<<Lq/256, 256>>>(I);
    k_scan <<<NP, 256>>>();
    k_fill <<<Lq/256, 256>>>(I);
    k_M2   <<<dim3(NP, BH, ZSP), 1024, SMEM_M2>>>(Q, K, V);
    k_sav  <<<dim3(NJT, BH), 256, SMEM_SAV>>>(Q, K, V, O);
}

// round 16
// speedup vs baseline: 1.1933x; 1.0312x over previous
#include <cuda_runtime.h>
#include <math.h>

// B,H,L,D = 4,8,2048,64 ; FACTOR=5 -> sample_k = n_top = 40
#define Bq    4
#define Hq    8
#define Lq    2048
#define Dq    64
#define BH    (Bq*Hq)
#define SK    40
#define NT    40
#define NP    4            // K slices for k_M2
#define SL    (Lq/NP)      // 512 rows per slice
#define ZSP   4            // l-splits per (p,bh) in k_M2
#define ZL    (Lq/ZSP)     // 512 queries per z
#define LMAX  (ZL*SK)      // staged list worst case
#define NCH   64           // cumsum chunks
#define CHLEN (Lq/NCH)     // 32
#define NJT   16           // j-tiles (of 128) for fused score+AV
#define JT    (Lq/NJT)     // 128
#define SMEM_M2  (SL*Dq*4 + (ZL+1+3)*4 + LMAX*4)
// sav smem (bytes): qs4 | kt (reused as Vs) | P (topk scratch first) | mtop | dsum | ucnt
#define SAV_QS   0
#define SAV_KT   (SAV_QS + NT*16*16)        // 10240
#define SAV_P    (SAV_KT + JT*65*4)         // 43520 (20480 bytes)
#define SAV_MT   (SAV_P  + NT*JT*4)         // 64000
#define SAV_DS   (SAV_MT + NT*4)            // 64160
#define SAV_UC   (SAV_DS + NT*4)            // 64320
#define SMEM_SAV (SAV_UC + 64)              // 64384

// ---- device scratch (no allocations allowed) ----
__device__ int    g_cnt[NP][Lq];
__device__ int    g_off[NP][Lq+1];     // per-slice offsets (zero-based)
__device__ int    g_list[NP][Lq*SK];   // per-slice sample lists
__device__ float2 g_part2[NP*BH*Lq];
__device__ float  g_den[BH*NT];
__device__ float  g_part[BH*NJT*NT*Dq];
__device__ float  g_csum[BH*NCH*Dq];
__device__ int    g_ctr2[BH];          // k_sav tail-election counters

// ---------------------------------------------------------------------------
// Prep 1: counts; zero g_den and tail counters (per-launch determinism).
// ---------------------------------------------------------------------------
__global__ void k_cnt(const int* __restrict__ I) {
    int l = blockIdx.x*256 + threadIdx.x;          // grid 8
    if (l < BH*NT) g_den[l] = 0.f;
    if (l < BH) g_ctr2[l] = 0;
    int c0=0,c1=0,c2=0,c3=0;
    const int* r = I + l*SK;
    #pragma unroll
    for (int s = 0; s < SK; ++s) {
        int p = r[s] >> 9;
        c0 += (p==0); c1 += (p==1); c2 += (p==2); c3 += (p==3);
    }
    g_cnt[0][l]=c0; g_cnt[1][l]=c1; g_cnt[2][l]=c2; g_cnt[3][l]=c3;
}

// Prep 2: per-slice exclusive prefix (grid NP)
__global__ void k_scan() {
    __shared__ int wsum[8];
    int p = blockIdx.x;
    int tid = threadIdx.x, lane = tid & 31, wid = tid >> 5;
    int loc[8]; int s = 0;
    #pragma unroll
    for (int k = 0; k < 8; ++k) { loc[k] = s; s += g_cnt[p][tid*8+k]; }
    int v = s;
    #pragma unroll
    for (int o = 1; o < 32; o <<= 1) {
        int t = __shfl_up_sync(0xffffffffu, v, o);
        if (lane >= o) v += t;
    }
    if (lane == 31) wsum[wid] = v;
    __syncthreads();
    if (tid == 0) {
        int a = 0;
        #pragma unroll
        for (int i = 0; i < 8; ++i) { int t = wsum[i]; wsum[i] = a; a += t; }
    }
    __syncthreads();
    int excl = v - s + wsum[wid];
    #pragma unroll
    for (int k = 0; k < 8; ++k) g_off[p][tid*8+k] = excl + loc[k];
    if (tid == 255) g_off[p][Lq] = excl + s;
}

// Prep 3: fill per-slice lists
__global__ void k_fill(const int* __restrict__ I) {
    int l = blockIdx.x*256 + threadIdx.x;
    int o0=g_off[0][l], o1=g_off[1][l], o2=g_off[2][l], o3=g_off[3][l];
    const int* r = I + l*SK;
    #pragma unroll
    for (int s = 0; s < SK; ++s) {
        int j = r[s];
        int p = j >> 9, jj = j & (SL-1);
        if      (p==0) g_list[0][o0++] = jj;
        else if (p==1) g_list[1][o1++] = jj;
        else if (p==2) g_list[2][o2++] = jj;
        else           g_list[3][o3++] = jj;
    }
}

// ---------------------------------------------------------------------------
// k_M2: proven R14 config (76us) + csum1 epilogue. NO tail.
// ---------------------------------------------------------------------------
__global__ void __launch_bounds__(1024) k_M2(const float* __restrict__ Q,
                                             const float* __restrict__ K,
                                             const float* __restrict__ V) {
    extern __shared__ float ks[];
    float4* ks4 = (float4*)ks;
    int* so = (int*)(ks + SL*Dq);
    int* sl = so + (ZL+1+3);
    int p = blockIdx.x, bh = blockIdx.y, z = blockIdx.z;
    int tid = threadIdx.x, warp = tid >> 5, lane = tid & 31;
    int g = lane >> 3, e = lane & 7;
    int zl0 = z*ZL;

    const float4* Ks = (const float4*)(K + ((size_t)bh*Lq + (size_t)p*SL)*Dq);
    for (int i = tid; i < SL*(Dq/4); i += 1024) ks4[i] = Ks[i];

    int sbeg = g_off[p][zl0];
    int send = g_off[p][zl0 + ZL];
    for (int i = tid; i <= ZL; i += 1024) so[i] = g_off[p][zl0 + i] - sbeg;
    for (int i = tid; i < send - sbeg; i += 1024) sl[i] = g_list[p][sbeg + i];
    __syncthreads();

    const float4* Q4 = (const float4*)Q;
    int l0 = zl0 + warp;
    #pragma unroll 1
    for (int i = 0; i < 16; i += 2) {
        int la = l0 + 32*i, lb = la + 32;
        int lla = warp + 32*i, llb = lla + 32;
        int a0 = so[lla], a1 = so[lla+1];
        int b0 = so[llb], b1 = so[llb+1];
        size_t qra = ((size_t)bh*Lq + la)*16;
        size_t qrb = ((size_t)bh*Lq + lb)*16;
        float4 qa0 = Q4[qra + e], qa1 = Q4[qra + e + 8];
        float4 qb0 = Q4[qrb + e], qb1 = Q4[qrb + e + 8];
        float mx0 = -INFINITY, sm0 = 0.f, mx1 = -INFINITY, sm1 = 0.f;
        int c0 = a0, c1 = b0;
        while (c0 < a1 || c1 < b1) {
            float pr0 = 0.f, pr1 = 0.f;
            bool v0 = false, v1 = false;
            if (c0 < a1) {
                int idx = c0 + g; v0 = idx < a1;
                int j = sl[v0 ? idx : a0];
                const float4* kb = ks4 + (j << 4);
                float4 x = kb[e], y = kb[e + 8];
                pr0 = qa0.x*x.x + qa0.y*x.y + qa0.z*x.z + qa0.w*x.w
                    + qa1.x*y.x + qa1.y*y.y + qa1.z*y.z + qa1.w*y.w;
            }
            if (c1 < b1) {
                int idx = c1 + g; v1 = idx < b1;
                int j = sl[v1 ? idx : b0];
                const float4* kb = ks4 + (j << 4);
                float4 x = kb[e], y = kb[e + 8];
                pr1 = qb0.x*x.x + qb0.y*x.y + qb0.z*x.z + qb0.w*x.w
                    + qb1.x*y.x + qb1.y*y.y + qb1.z*y.z + qb1.w*y.w;
            }
            pr0 += __shfl_xor_sync(0xffffffffu, pr0, 1);
            pr1 += __shfl_xor_sync(0xffffffffu, pr1, 1);
            pr0 += __shfl_xor_sync(0xffffffffu, pr0, 2);
            pr1 += __shfl_xor_sync(0xffffffffu, pr1, 2);
            pr0 += __shfl_xor_sync(0xffffffffu, pr0, 4);
            pr1 += __shfl_xor_sync(0xffffffffu, pr1, 4);
            if (v0) { mx0 = fmaxf(mx0, pr0); sm0 += pr0; }
            if (v1) { mx1 = fmaxf(mx1, pr1); sm1 += pr1; }
            c0 += 4; c1 += 4;
        }
        mx0 = fmaxf(mx0, __shfl_xor_sync(0xffffffffu, mx0, 8));
        mx0 = fmaxf(mx0, __shfl_xor_sync(0xffffffffu, mx0, 16));
        sm0 += __shfl_xor_sync(0xffffffffu, sm0, 8);
        sm0 += __shfl_xor_sync(0xffffffffu, sm0, 16);
        mx1 = fmaxf(mx1, __shfl_xor_sync(0xffffffffu, mx1, 8));
        mx1 = fmaxf(mx1, __shfl_xor_sync(0xffffffffu, mx1, 16));
        sm1 += __shfl_xor_sync(0xffffffffu, sm1, 8);
        sm1 += __shfl_xor_sync(0xffffffffu, sm1, 16);
        if (lane == 0) {
            g_part2[((size_t)p*BH + bh)*Lq + la] = make_float2(mx0, sm0);
            g_part2[((size_t)p*BH + bh)*Lq + lb] = make_float2(mx1, sm1);
        }
    }

    // ---- csum1 epilogue: first 128 blocks compute V chunk sums ----
    int mbid = blockIdx.x + NP*blockIdx.y + NP*BH*blockIdx.z;
    if (mbid < (NCH*BH)/16) {
        int gcid = mbid*16 + (tid >> 6);
        int d = tid & 63;
        int cbh = gcid >> 6, ch = gcid & (NCH-1);
        const float* v = V + ((size_t)cbh*Lq + ch*CHLEN)*Dq + d;
        float a = 0.f;
        #pragma unroll
        for (int l = 0; l < CHLEN; l += 4) {
            float x0 = v[(size_t)l*Dq],     x1 = v[(size_t)(l+1)*Dq];
            float x2 = v[(size_t)(l+2)*Dq], x3 = v[(size_t)(l+3)*Dq];
            a += (x0+x1) + (x2+x3);
        }
        g_csum[(cbh*NCH + ch)*Dq + d] = a;
    }
}

// ---------------------------------------------------------------------------
// k_sav: per-block REDUNDANT top-40 radix select (deterministic; scratch in
// the dead P buffer), then fused score+exp+AV + cumsum epilogue + fix tail.
// ---------------------------------------------------------------------------
__global__ void __launch_bounds__(256, 3) k_sav(const float* __restrict__ Q,
                                                const float* __restrict__ K,
                                                const float* __restrict__ V,
                                                float* __restrict__ O) {
    extern __shared__ char sm_raw[];
    float4* qs4  = (float4*)(sm_raw + SAV_QS);
    float*  kt   = (float*) (sm_raw + SAV_KT);   // K tile, then V tile
    float*  P    = (float*) (sm_raw + SAV_P);
    int*    mtop = (int*)   (sm_raw + SAV_MT);
    float*  dsum = (float*) (sm_raw + SAV_DS);
    int*    puc  = (int*)   (sm_raw + SAV_UC);

    int jtx = blockIdx.x, bh = blockIdx.y;
    int jt0 = jtx * JT;
    int tid = threadIdx.x, lane = tid & 31, wwid = tid >> 5;
    int j = tid & (JT-1), half = tid >> 7;

    // ---- Phase 0: top-40 select for this bh (scratch = P buffer) ----
    unsigned* keys = (unsigned*)(sm_raw + SAV_P);            // 8KB
    int*      tie  = (int*)(sm_raw + SAV_P + Lq*4);          // 8KB
    __shared__ int hist[256];
    __shared__ int wsc[8];
    __shared__ int tops[NT];
    __shared__ int s_d, s_acc, s_ngt, s_ntie;

    for (int i = tid; i < Lq; i += 256) {
        float mx = -INFINITY, sm = 0.f;
        #pragma unroll
        for (int pp = 0; pp < NP; ++pp) {
            float2 v = g_part2[((size_t)pp*BH + bh)*Lq + i];
            mx = fmaxf(mx, v.x); sm += v.y;
        }
        float m = mx - sm * (1.0f/(float)Lq);
        unsigned u = __float_as_uint(m);
        keys[i] = (u & 0x80000000u) ? ~u : (u | 0x80000000u);
    }
    if (tid == 0) { s_ngt = 0; s_ntie = 0; }
    __syncthreads();

    unsigned prefix = 0; int kk = NT;
    #pragma unroll
    for (int level = 3; level >= 0; --level) {
        int sh = level*8;
        hist[tid] = 0;
        __syncthreads();
        unsigned maskAbove = (level==3) ? 0u : (0xFFFFFFFFu << (sh+8));
        for (int i = tid; i < Lq; i += 256) {
            unsigned key = keys[i];
            if ((key & maskAbove) == prefix)
                atomicAdd(&hist[(key >> sh) & 255], 1);
        }
        __syncthreads();
        // parallel digit pick: reversed inclusive scan over hist
        int hv = hist[255 - tid];
        int x = hv;
        #pragma unroll
        for (int o = 1; o < 32; o <<= 1) {
            int t = __shfl_up_sync(0xffffffffu, x, o);
            if (lane >= o) x += t;
        }
        if (lane == 31) wsc[wwid] = x;
        __syncthreads();
        if (wwid == 0 && lane < 8) {
            int y = wsc[lane], inc = y;
            #pragma unroll
            for (int o = 1; o < 8; o <<= 1) {
                int t = __shfl_up_sync(0xffu, inc, o);
                if (lane >= o) inc += t;
            }
            wsc[lane] = inc - y;
        }
        __syncthreads();
        x += wsc[wwid];
        int above = x - hv;                  // # keys with digit > (255-tid)
        if (x >= kk && above < kk) { s_d = 255 - tid; s_acc = above; }
        __syncthreads();
        kk -= s_acc;
        prefix |= ((unsigned)s_d) << sh;
        __syncthreads();
    }
    unsigned T = prefix;

    for (int i = tid; i < Lq; i += 256) {
        unsigned key = keys[i];
        if (key > T)       { int pos = atomicAdd(&s_ngt, 1);  tops[pos] = i; }
        else if (key == T) { int pos = atomicAdd(&s_ntie, 1); tie[pos]  = i; }
    }
    __syncthreads();
    int ngt = s_ngt, ntie = s_ntie;          // kk still needed from ties
    if (tid < 32) {
        for (int t = 0; t < kk; ++t) {
            long long best = 0x7FFFFFFFFFFFFFFFLL;
            for (int i = tid; i < ntie; i += 32) {
                long long c = ((long long)tie[i] << 32) | (unsigned)i;
                if (c < best) best = c;
            }
            #pragma unroll
            for (int o = 16; o; o >>= 1) {
                long long c = __shfl_xor_sync(0xffffffffu, best, o);
                if (c < best) best = c;
            }
            if (tid == 0) {
                int slot = (int)(best & 0xffffffffu);
                tops[ngt + t] = (int)(best >> 32);
                tie[slot] = 0x7FFFFFFF;
            }
            __syncwarp();
        }
    }
    __syncthreads();

    // rank-sort desc by row index -> canonical mtop (atomics order erased)
    if (tid < NT) {
        int me = tops[tid], r = 0;
        #pragma unroll
        for (int jj = 0; jj < NT; ++jj) r += (tops[jj] > me);
        mtop[r] = me;
    }
    if (tid < NT) dsum[tid] = 0.f;
    __syncthreads();
    if (tid == 0) {
        int c = 0;
        while (c < NT && mtop[c] >= jt0) ++c;
        *puc = c;
    }

    // ---- stage Qr + K tile ----
    const float4* Q4 = (const float4*)Q;
    for (int i = tid; i < NT*16; i += 256) {
        int u = i >> 4, d4 = i & 15;
        qs4[i] = Q4[((size_t)bh*Lq + mtop[u])*16 + d4];
    }
    const float4* K4 = (const float4*)K;
    for (int i = tid; i < JT*16; i += 256) {
        int r = i >> 4, c4 = i & 15;
        float4 v = K4[((size_t)bh*Lq + jt0 + r)*16 + c4];
        kt[r*65 + c4*4+0] = v.x; kt[r*65 + c4*4+1] = v.y;
        kt[r*65 + c4*4+2] = v.z; kt[r*65 + c4*4+3] = v.w;
    }
    __syncthreads();
    int ucnt = *puc;

    // extract K row into registers; kt bytes are dead afterwards
    float kr[Dq];
    #pragma unroll
    for (int d = 0; d < Dq; ++d) kr[d] = kt[j*65 + d];
    __syncthreads();                       // everyone done reading kt

    // stage V tile into the former kt bytes (overlaps with phase A compute)
    float* Vs = kt;                        // [JT][Dq] row-major
    float4* Vs4 = (float4*)Vs;
    const float4* V4 = (const float4*)V;
    for (int i = tid; i < JT*16; i += 256)
        Vs4[i] = V4[((size_t)bh*Lq + jt0)*16 + i];

    // ---- Phase A: scores -> exp -> smem P (live u only) ----
    int jg = jt0 + j;
    #pragma unroll 1
    for (int u = half; u < ucnt; u += 2) {
        int m = mtop[u];
        float s = 0.f;
        #pragma unroll
        for (int d4 = 0; d4 < 16; ++d4) {
            float4 qv = qs4[u*16 + d4];
            s += kr[d4*4+0]*qv.x + kr[d4*4+1]*qv.y + kr[d4*4+2]*qv.z + kr[d4*4+3]*qv.w;
        }
        float e = (jg > m) ? 0.f : __expf(s * 0.125f);
        P[u*JT + j] = e;
        float v = e;
        v += __shfl_xor_sync(0xffffffffu, v, 1);
        v += __shfl_xor_sync(0xffffffffu, v, 2);
        v += __shfl_xor_sync(0xffffffffu, v, 4);
        v += __shfl_xor_sync(0xffffffffu, v, 8);
        v += __shfl_xor_sync(0xffffffffu, v, 16);
        if (lane == 0) atomicAdd(&dsum[u], v);
    }
    __syncthreads();                       // P + Vs both ready
    if (tid < NT) atomicAdd(&g_den[bh*NT + tid], dsum[tid]);

    // ---- Phase B: AV partials from smem P + smem Vs ----
    int d = tid & 63, ug = tid >> 6;
    const float4* P4 = (const float4*)P;
    float acc[10];
    #pragma unroll
    for (int k = 0; k < 10; ++k) acc[k] = 0.f;

    #pragma unroll 1
    for (int j4 = 0; j4 < JT/4; ++j4) {
        float v0 = Vs[(j4*4+0)*Dq + d], v1 = Vs[(j4*4+1)*Dq + d];
        float v2 = Vs[(j4*4+2)*Dq + d], v3 = Vs[(j4*4+3)*Dq + d];
        #pragma unroll
        for (int k = 0; k < 10; ++k) {
            int u = ug*10 + k;
            if (u < ucnt) {
                float4 pv = P4[u*(JT/4) + j4];
                acc[k] += pv.x*v0 + pv.y*v1 + pv.z*v2 + pv.w*v3;
            }
        }
    }
    #pragma unroll
    for (int k = 0; k < 10; ++k)
        g_part[(((size_t)bh*NJT + jtx)*NT + ug*10 + k)*Dq + d] = acc[k];

    // ---- Epilogue: cumsum output for one chunk-group (no scatter) ----
    {
        int sbid = jtx + NJT*bh;                 // [0, 512)
        int cbh = sbid >> 4;                     // == bh
        int ch = (sbid & 15)*4 + (tid >> 6);
        int dd = tid & 63;
        float a = 0.f;
        int c = 0;
        for (; c + 4 <= ch; c += 4) {
            float x0 = g_csum[(cbh*NCH + c+0)*Dq + dd];
            float x1 = g_csum[(cbh*NCH + c+1)*Dq + dd];
            float x2 = g_csum[(cbh*NCH + c+2)*Dq + dd];
            float x3 = g_csum[(cbh*NCH + c+3)*Dq + dd];
            a += (x0+x1) + (x2+x3);
        }
        for (; c < ch; ++c) a += g_csum[(cbh*NCH + c)*Dq + dd];

        size_t base = ((size_t)cbh*Lq + ch*CHLEN)*Dq + dd;
        #pragma unroll 4
        for (int l = 0; l < CHLEN; ++l) {
            a += V[base + (size_t)l*Dq];
            O[base + (size_t)l*Dq] = a;
        }
    }

    // ---- tail election: last of the 16 blocks for this bh runs the fix ----
    __shared__ int s_last2;
    if (tid == 0) {
        __threadfence();
        int c = atomicAdd(&g_ctr2[bh], 1);
        s_last2 = (c == NJT - 1);
    }
    __syncthreads();
    if (!s_last2) return;
    __threadfence();                       // acquire g_part/g_den/O writes

    for (int i = tid; i < NT*Dq; i += 256) {
        int u = i >> 6, dd = i & 63;
        int row = mtop[u];
        float acc2 = 0.f;
        #pragma unroll
        for (int js = 0; js < NJT; ++js)
            acc2 += g_part[(((size_t)bh*NJT + js)*NT + u)*Dq + dd];
        O[((size_t)bh*Lq + row)*Dq + dd] = acc2 / g_den[bh*NT + u];
    }
}

extern "C" void kernel_launch(void* const* d_in, const int* in_sizes, int n_in,
                              void* d_out, int out_size) {
    const float* Q = (const float*)d_in[0];
    const float* K = (const float*)d_in[1];
    const float* V = (const float*)d_in[2];
    const int*   I = (const int*)  d_in[3];
    float* O = (float*)d_out;

    cudaFuncSetAttribute(k_M2,  cudaFuncAttributeMaxDynamicSharedMemorySize, SMEM_M2);
    cudaFuncSetAttribute(k_sav, cudaFuncAttributeMaxDynamicSharedMemorySize, SMEM_SAV);

    k_cnt  <<<Lq/256, 256>>>(I);
    k_scan <<<NP, 256>>>();
    k_fill <<<Lq/256, 256>>>(I);
    k_M2   <<<dim3(NP, BH, ZSP), 1024, SMEM_M2>>>(Q, K, V);
    k_sav  <<<dim3(NJT, BH), 256, SMEM_SAV>>>(Q, K, V, O);
}